// round 3
// baseline (speedup 1.0000x reference)
#include <cuda_runtime.h>

#define NPTS 262144
#define PPL 128
#define DD 64
#define PN ((size_t)PPL * (size_t)NPTS)

// Scratch (no allocation allowed -> __device__ globals)
__device__ float g_h2[(size_t)NPTS * DD];   // 64 MB: fc2 features (post BN+ReLU)
__device__ float g_scores[NPTS];            // 1 MB : relu(fc3) scores

// ---------------------------------------------------------------------------
// Kernel 1: per-point MLP. 128 points/block, 1 point/thread, 64 accumulators.
// Shared: weight tile (64x64) + transposed feature/h1 tile (stride 129).
// ---------------------------------------------------------------------------
#define MLP_TPB 128
#define SH_W_FLOATS 4096            // 64x64 weight tile
#define SH_F_FLOATS (64 * 129)      // transposed activation tile, padded
#define MLP_SMEM_BYTES ((SH_W_FLOATS + SH_F_FLOATS) * 4)

__global__ void __launch_bounds__(MLP_TPB) mlp_kernel(
    const float* __restrict__ feature, const float* __restrict__ feature_geo,
    const float* __restrict__ w1, const float* __restrict__ b1,
    const float* __restrict__ g1, const float* __restrict__ be1,
    const float* __restrict__ m1, const float* __restrict__ v1,
    const float* __restrict__ w2, const float* __restrict__ b2,
    const float* __restrict__ g2, const float* __restrict__ be2,
    const float* __restrict__ m2, const float* __restrict__ v2,
    const float* __restrict__ w3, const float* __restrict__ b3)
{
    extern __shared__ float smem[];
    float* sh_w = smem;                 // SH_W_FLOATS
    float* sh_f = smem + SH_W_FLOATS;   // SH_F_FLOATS

    __shared__ float A1[64], C1[64], A2[64], C2[64], W3s[64];
    __shared__ float B3;

    const int tid = threadIdx.x;
    const int base = blockIdx.x * MLP_TPB;
    const int n = base + tid;

    // Fold BN into per-channel scale/offset: relu(acc*A + C)
    if (tid < 64) {
        float s1 = g1[tid] * rsqrtf(v1[tid] + 1e-5f);
        A1[tid] = s1;
        C1[tid] = (b1[tid] - m1[tid]) * s1 + be1[tid];
        float s2 = g2[tid] * rsqrtf(v2[tid] + 1e-5f);
        A2[tid] = s2;
        C2[tid] = (b2[tid] - m2[tid]) * s2 + be2[tid];
        W3s[tid] = w3[tid];
        if (tid == 0) B3 = b3[0];
    }

    float acc[64];
    #pragma unroll
    for (int j = 0; j < 64; j++) acc[j] = 0.f;

    // ---- Layer 1: K=128 in two halves (half 0 = feature, half 1 = feature_geo)
    for (int kh = 0; kh < 2; kh++) {
        __syncthreads();  // buffers free to overwrite (also covers A1/C1 init)
        // stage weight half: w1 rows [kh*64, kh*64+64)
        {
            const float4* wsrc = (const float4*)(w1 + kh * 4096);
            float4* wdst = (float4*)sh_w;
            #pragma unroll
            for (int i = tid; i < 1024; i += MLP_TPB) wdst[i] = wsrc[i];
        }
        // stage activations transposed: sh_f[k][pt], pt-stride 129 (bank-safe)
        {
            const float* src = kh ? feature_geo : feature;
            const float4* fsrc = (const float4*)(src + (size_t)base * 64);
            #pragma unroll
            for (int idx = tid; idx < 2048; idx += MLP_TPB) {
                float4 v = fsrc[idx];
                int pt = idx >> 4;
                int kk = (idx & 15) * 4;
                sh_f[(kk + 0) * 129 + pt] = v.x;
                sh_f[(kk + 1) * 129 + pt] = v.y;
                sh_f[(kk + 2) * 129 + pt] = v.z;
                sh_f[(kk + 3) * 129 + pt] = v.w;
            }
        }
        __syncthreads();
        #pragma unroll 4
        for (int kk = 0; kk < 64; kk++) {
            float fk = sh_f[kk * 129 + tid];
            const float4* wr = (const float4*)(sh_w + kk * 64);
            #pragma unroll
            for (int j4 = 0; j4 < 16; j4++) {
                float4 w = wr[j4];
                acc[4 * j4 + 0] = fmaf(fk, w.x, acc[4 * j4 + 0]);
                acc[4 * j4 + 1] = fmaf(fk, w.y, acc[4 * j4 + 1]);
                acc[4 * j4 + 2] = fmaf(fk, w.z, acc[4 * j4 + 2]);
                acc[4 * j4 + 3] = fmaf(fk, w.w, acc[4 * j4 + 3]);
            }
        }
    }

    // BN1 + ReLU -> h1 transposed into sh_f column tid.
    // Safe without sync: column tid is read/written only by thread tid.
    #pragma unroll
    for (int j = 0; j < 64; j++) {
        float h = fmaf(acc[j], A1[j], C1[j]);
        sh_f[j * 129 + tid] = fmaxf(h, 0.f);
        acc[j] = 0.f;
    }
    __syncthreads();  // everyone done with layer-1 weight reads
    {
        const float4* wsrc = (const float4*)w2;
        float4* wdst = (float4*)sh_w;
        #pragma unroll
        for (int i = tid; i < 1024; i += MLP_TPB) wdst[i] = wsrc[i];
    }
    __syncthreads();

    // ---- Layer 2: K=64
    #pragma unroll 4
    for (int kk = 0; kk < 64; kk++) {
        float hk = sh_f[kk * 129 + tid];
        const float4* wr = (const float4*)(sh_w + kk * 64);
        #pragma unroll
        for (int j4 = 0; j4 < 16; j4++) {
            float4 w = wr[j4];
            acc[4 * j4 + 0] = fmaf(hk, w.x, acc[4 * j4 + 0]);
            acc[4 * j4 + 1] = fmaf(hk, w.y, acc[4 * j4 + 1]);
            acc[4 * j4 + 2] = fmaf(hk, w.z, acc[4 * j4 + 2]);
            acc[4 * j4 + 3] = fmaf(hk, w.w, acc[4 * j4 + 3]);
        }
    }

    // BN2 + ReLU -> h2, fc3 score, stores
    float s = 0.f;
    float* hrow = g_h2 + (size_t)n * 64;
    #pragma unroll
    for (int j4 = 0; j4 < 16; j4++) {
        float4 o;
        o.x = fmaxf(fmaf(acc[4 * j4 + 0], A2[4 * j4 + 0], C2[4 * j4 + 0]), 0.f);
        o.y = fmaxf(fmaf(acc[4 * j4 + 1], A2[4 * j4 + 1], C2[4 * j4 + 1]), 0.f);
        o.z = fmaxf(fmaf(acc[4 * j4 + 2], A2[4 * j4 + 2], C2[4 * j4 + 2]), 0.f);
        o.w = fmaxf(fmaf(acc[4 * j4 + 3], A2[4 * j4 + 3], C2[4 * j4 + 3]), 0.f);
        s = fmaf(o.x, W3s[4 * j4 + 0], s);
        s = fmaf(o.y, W3s[4 * j4 + 1], s);
        s = fmaf(o.z, W3s[4 * j4 + 2], s);
        s = fmaf(o.w, W3s[4 * j4 + 3], s);
        ((float4*)hrow)[j4] = o;
    }
    g_scores[n] = fmaxf(s + B3, 0.f);
}

// ---------------------------------------------------------------------------
// Kernel 2: zero the pooled-feature region (atomicMax accumulates into it)
// ---------------------------------------------------------------------------
__global__ void zero_feats(float* __restrict__ out) {
    size_t i = (size_t)blockIdx.x * 256 + threadIdx.x;  // 16384 elements
    out[4 * PN + i] = 0.f;
}

// ---------------------------------------------------------------------------
// Kernel 3: per-(plane, point-chunk) masks + compacted masked max-pool.
// grid = (N/2048, P), 256 threads, 8 points/thread.
// ---------------------------------------------------------------------------
#define P2_TPB 256
#define P2_PTS 2048
#define P2_ITERS 8

__global__ void __launch_bounds__(P2_TPB) plane_kernel(
    const float* __restrict__ xyz, const float* __restrict__ centers,
    const float* __restrict__ plane_center, const float* __restrict__ plane_normal,
    const float* __restrict__ pmin, const float* __restrict__ pmax,
    float* __restrict__ out)
{
    const int p = blockIdx.y;
    const int base = blockIdx.x * P2_PTS;
    const int tid = threadIdx.x;

    __shared__ unsigned shOn[64], shOff[64];
    __shared__ int lstOn[P2_PTS];
    __shared__ int lstOff[P2_PTS];
    __shared__ int cntOn, cntOff;
    if (tid == 0) { cntOn = 0; cntOff = 0; }
    if (tid < 64) { shOn[tid] = 0u; shOff[tid] = 0u; }

    const float nx = plane_normal[p * 3 + 0];
    const float ny = plane_normal[p * 3 + 1];
    const float nz = plane_normal[p * 3 + 2];
    const float off = plane_center[p * 3 + 0] * nx
                    + plane_center[p * 3 + 1] * ny
                    + plane_center[p * 3 + 2] * nz;
    const float mn0 = pmin[p * 3 + 0], mn1 = pmin[p * 3 + 1], mn2 = pmin[p * 3 + 2];
    const float mx0 = pmax[p * 3 + 0], mx1 = pmax[p * 3 + 1], mx2 = pmax[p * 3 + 2];
    const bool a0 = (mx0 != 0.f), a1 = (mx1 != 0.f), a2 = (mx2 != 0.f);
    const float cx = centers[0], cy = centers[1], cz = centers[2];

    __syncthreads();

    float* oS  = out;
    float* oM  = out + PN;
    float* oOn = out + 2 * PN;
    float* oOf = out + 3 * PN;
    const size_t rowoff = (size_t)p * NPTS;

    #pragma unroll
    for (int i = 0; i < P2_ITERS; i++) {
        int n = base + i * P2_TPB + tid;
        float px = xyz[n * 3 + 0] + cx;
        float py = xyz[n * 3 + 1] + cy;
        float pz = xyz[n * 3 + 2] + cz;
        bool rok = (!a0 || (px >= mn0 && px < mx0))
                && (!a1 || (py >= mn1 && py < mx1))
                && (!a2 || (pz >= mn2 && pz < mx2));
        float dist = fabsf(px * nx + py * ny + pz * nz - off);
        bool mask = rok && (dist < 0.1f);
        float s = g_scores[n];
        // sigmoid(s) > 0.5  <=>  s > 0   (s >= 0 from relu)
        bool onm  = mask && (s > 0.f);
        bool offm = mask && (s <= 0.f);
        size_t o = rowoff + n;
        oS[o]  = mask ? s : 0.f;
        oM[o]  = mask ? 1.f : 0.f;
        oOn[o] = onm ? 1.f : 0.f;
        oOf[o] = offm ? 1.f : 0.f;
        if (onm)       lstOn[atomicAdd(&cntOn, 1)] = n;
        else if (offm) lstOff[atomicAdd(&cntOff, 1)] = n;
    }
    __syncthreads();

    // Cooperative masked max-pool of h2 rows: 4 rows in flight x 64 dims.
    const int d = tid & 63;
    const int g = tid >> 6;
    unsigned mOn = 0u, mOf = 0u;
    const int con = cntOn, cof = cntOff;
    for (int idx = g; idx < con; idx += 4) {
        int n = lstOn[idx];
        mOn = max(mOn, __float_as_uint(g_h2[(size_t)n * 64 + d]));
    }
    for (int idx = g; idx < cof; idx += 4) {
        int n = lstOff[idx];
        mOf = max(mOf, __float_as_uint(g_h2[(size_t)n * 64 + d]));
    }
    if (mOn) atomicMax(&shOn[d], mOn);
    if (mOf) atomicMax(&shOff[d], mOf);
    __syncthreads();

    // h2 >= 0 so uint-bit atomicMax against 0-initialized output is exact.
    if (tid < 64) {
        unsigned v = shOn[tid];
        if (v) atomicMax((unsigned*)(out + 4 * PN + (size_t)p * 64 + tid), v);
    } else if (tid < 128) {
        unsigned v = shOff[tid - 64];
        if (v) atomicMax((unsigned*)(out + 4 * PN + (size_t)PPL * 64 + (size_t)p * 64 + (tid - 64)), v);
    }
}

// ---------------------------------------------------------------------------
extern "C" void kernel_launch(void* const* d_in, const int* in_sizes, int n_in,
                              void* d_out, int out_size) {
    const float* feature      = (const float*)d_in[0];
    const float* feature_geo  = (const float*)d_in[1];
    const float* xyz          = (const float*)d_in[2];
    const float* centers      = (const float*)d_in[3];
    const float* plane_center = (const float*)d_in[4];
    const float* plane_normal = (const float*)d_in[5];
    const float* pxyz_min     = (const float*)d_in[6];
    const float* pxyz_max     = (const float*)d_in[7];
    const float* w1 = (const float*)d_in[8];
    const float* b1 = (const float*)d_in[9];
    const float* g1 = (const float*)d_in[10];
    const float* be1 = (const float*)d_in[11];
    const float* m1 = (const float*)d_in[12];
    const float* v1 = (const float*)d_in[13];
    const float* w2 = (const float*)d_in[14];
    const float* b2 = (const float*)d_in[15];
    const float* g2 = (const float*)d_in[16];
    const float* be2 = (const float*)d_in[17];
    const float* m2 = (const float*)d_in[18];
    const float* v2 = (const float*)d_in[19];
    const float* w3 = (const float*)d_in[20];
    const float* b3 = (const float*)d_in[21];
    float* out = (float*)d_out;

    cudaFuncSetAttribute((const void*)mlp_kernel,
                         cudaFuncAttributeMaxDynamicSharedMemorySize,
                         MLP_SMEM_BYTES);

    zero_feats<<<64, 256>>>(out);
    mlp_kernel<<<NPTS / MLP_TPB, MLP_TPB, MLP_SMEM_BYTES>>>(
        feature, feature_geo,
        w1, b1, g1, be1, m1, v1,
        w2, b2, g2, be2, m2, v2,
        w3, b3);
    dim3 grid2(NPTS / P2_PTS, PPL);
    plane_kernel<<<grid2, P2_TPB>>>(xyz, centers, plane_center, plane_normal,
                                    pxyz_min, pxyz_max, out);
}

// round 5
// speedup vs baseline: 1.0480x; 1.0480x over previous
#include <cuda_runtime.h>

#define NPTS 262144
#define PPL 128
#define DD 64
#define PN ((size_t)PPL * (size_t)NPTS)

typedef unsigned long long u64;

// Scratch (no allocation allowed -> __device__ globals)
__device__ float g_h2[(size_t)NPTS * DD];   // 64 MB: fc2 features (post BN+ReLU)
__device__ float g_scores[NPTS];            // 1 MB : relu(fc3) scores

// ---------------------------------------------------------------------------
// Packed f32x2 helpers (FFMA2 — bit-exact pair of fp32 FMAs, 2x fma-pipe rate)
// ---------------------------------------------------------------------------
__device__ __forceinline__ u64 pack_dup(float x) {
    u64 r;
    asm("mov.b64 %0, {%1, %1};" : "=l"(r) : "f"(x));
    return r;
}
__device__ __forceinline__ u64 pack2(float lo, float hi) {
    u64 r;
    asm("mov.b64 %0, {%1, %2};" : "=l"(r) : "f"(lo), "f"(hi));
    return r;
}
__device__ __forceinline__ void unpack2(u64 v, float& lo, float& hi) {
    asm("mov.b64 {%0, %1}, %2;" : "=f"(lo), "=f"(hi) : "l"(v));
}
__device__ __forceinline__ void ffma2(u64& acc, u64 a, u64 b) {
    asm("fma.rn.f32x2 %0, %1, %2, %0;" : "+l"(acc) : "l"(a), "l"(b));
}

// ---------------------------------------------------------------------------
// Kernel 1: per-point MLP. 128 points/block, 1 point/thread.
// Accumulators are 32 packed channel-pairs -> FFMA2 inner loop.
// ---------------------------------------------------------------------------
#define MLP_TPB 128
#define SH_W_FLOATS 4096            // 64x64 weight tile
#define SH_F_FLOATS (64 * 129)      // transposed activation tile, padded
#define MLP_SMEM_BYTES ((SH_W_FLOATS + SH_F_FLOATS) * 4)

__global__ void __launch_bounds__(MLP_TPB) mlp_kernel(
    const float* __restrict__ feature, const float* __restrict__ feature_geo,
    const float* __restrict__ w1, const float* __restrict__ b1,
    const float* __restrict__ g1, const float* __restrict__ be1,
    const float* __restrict__ m1, const float* __restrict__ v1,
    const float* __restrict__ w2, const float* __restrict__ b2,
    const float* __restrict__ g2, const float* __restrict__ be2,
    const float* __restrict__ m2, const float* __restrict__ v2,
    const float* __restrict__ w3, const float* __restrict__ b3)
{
    extern __shared__ float smem[];
    float* sh_w = smem;                 // SH_W_FLOATS
    float* sh_f = smem + SH_W_FLOATS;   // SH_F_FLOATS

    __shared__ float A1[64], C1[64], A2[64], C2[64], W3s[64];
    __shared__ float B3;

    const int tid = threadIdx.x;
    const int base = blockIdx.x * MLP_TPB;
    const int n = base + tid;

    // Fold BN into per-channel scale/offset: relu(acc*A + C)
    if (tid < 64) {
        float s1 = g1[tid] * rsqrtf(v1[tid] + 1e-5f);
        A1[tid] = s1;
        C1[tid] = (b1[tid] - m1[tid]) * s1 + be1[tid];
        float s2 = g2[tid] * rsqrtf(v2[tid] + 1e-5f);
        A2[tid] = s2;
        C2[tid] = (b2[tid] - m2[tid]) * s2 + be2[tid];
        W3s[tid] = w3[tid];
        if (tid == 0) B3 = b3[0];
    }

    u64 acc[32];                        // channel pairs (2i, 2i+1)
    #pragma unroll
    for (int i = 0; i < 32; i++) acc[i] = 0ull;

    // ---- Layer 1: K=128 in two halves (half 0 = feature, half 1 = feature_geo)
    for (int kh = 0; kh < 2; kh++) {
        __syncthreads();  // buffers free to overwrite (also covers A1/C1 init)
        // stage weight half: w1 rows [kh*64, kh*64+64)
        {
            const float4* wsrc = (const float4*)(w1 + kh * 4096);
            float4* wdst = (float4*)sh_w;
            #pragma unroll
            for (int i = tid; i < 1024; i += MLP_TPB) wdst[i] = wsrc[i];
        }
        // stage activations transposed: sh_f[k][pt], pt-stride 129 (bank-safe)
        {
            const float* src = kh ? feature_geo : feature;
            const float4* fsrc = (const float4*)(src + (size_t)base * 64);
            #pragma unroll
            for (int idx = tid; idx < 2048; idx += MLP_TPB) {
                float4 v = fsrc[idx];
                int pt = idx >> 4;
                int kk = (idx & 15) * 4;
                sh_f[(kk + 0) * 129 + pt] = v.x;
                sh_f[(kk + 1) * 129 + pt] = v.y;
                sh_f[(kk + 2) * 129 + pt] = v.z;
                sh_f[(kk + 3) * 129 + pt] = v.w;
            }
        }
        __syncthreads();
        #pragma unroll 4
        for (int kk = 0; kk < 64; kk++) {
            u64 fk2 = pack_dup(sh_f[kk * 129 + tid]);
            const float4* wr = (const float4*)(sh_w + kk * 64);
            #pragma unroll
            for (int j4 = 0; j4 < 16; j4++) {
                float4 w = wr[j4];
                ffma2(acc[2 * j4 + 0], fk2, pack2(w.x, w.y));
                ffma2(acc[2 * j4 + 1], fk2, pack2(w.z, w.w));
            }
        }
    }

    // BN1 + ReLU -> h1 transposed into sh_f column tid.
    // Safe without sync: column tid is read/written only by thread tid.
    #pragma unroll
    for (int i = 0; i < 32; i++) {
        float lo, hi;
        unpack2(acc[i], lo, hi);
        int j = 2 * i;
        sh_f[(j + 0) * 129 + tid] = fmaxf(fmaf(lo, A1[j + 0], C1[j + 0]), 0.f);
        sh_f[(j + 1) * 129 + tid] = fmaxf(fmaf(hi, A1[j + 1], C1[j + 1]), 0.f);
        acc[i] = 0ull;
    }
    __syncthreads();  // everyone done with layer-1 weight reads
    {
        const float4* wsrc = (const float4*)w2;
        float4* wdst = (float4*)sh_w;
        #pragma unroll
        for (int i = tid; i < 1024; i += MLP_TPB) wdst[i] = wsrc[i];
    }
    __syncthreads();

    // ---- Layer 2: K=64
    #pragma unroll 4
    for (int kk = 0; kk < 64; kk++) {
        u64 hk2 = pack_dup(sh_f[kk * 129 + tid]);
        const float4* wr = (const float4*)(sh_w + kk * 64);
        #pragma unroll
        for (int j4 = 0; j4 < 16; j4++) {
            float4 w = wr[j4];
            ffma2(acc[2 * j4 + 0], hk2, pack2(w.x, w.y));
            ffma2(acc[2 * j4 + 1], hk2, pack2(w.z, w.w));
        }
    }

    // BN2 + ReLU -> h2, fc3 score, stores
    float s = 0.f;
    float* hrow = g_h2 + (size_t)n * 64;
    #pragma unroll
    for (int j4 = 0; j4 < 16; j4++) {
        float a0, a1, a2, a3;
        unpack2(acc[2 * j4 + 0], a0, a1);
        unpack2(acc[2 * j4 + 1], a2, a3);
        float4 o;
        o.x = fmaxf(fmaf(a0, A2[4 * j4 + 0], C2[4 * j4 + 0]), 0.f);
        o.y = fmaxf(fmaf(a1, A2[4 * j4 + 1], C2[4 * j4 + 1]), 0.f);
        o.z = fmaxf(fmaf(a2, A2[4 * j4 + 2], C2[4 * j4 + 2]), 0.f);
        o.w = fmaxf(fmaf(a3, A2[4 * j4 + 3], C2[4 * j4 + 3]), 0.f);
        s = fmaf(o.x, W3s[4 * j4 + 0], s);
        s = fmaf(o.y, W3s[4 * j4 + 1], s);
        s = fmaf(o.z, W3s[4 * j4 + 2], s);
        s = fmaf(o.w, W3s[4 * j4 + 3], s);
        ((float4*)hrow)[j4] = o;
    }
    g_scores[n] = fmaxf(s + B3, 0.f);
}

// ---------------------------------------------------------------------------
// Kernel 2: zero the pooled-feature region (atomicMax accumulates into it)
// ---------------------------------------------------------------------------
__global__ void zero_feats(float* __restrict__ out) {
    size_t i = (size_t)blockIdx.x * 256 + threadIdx.x;  // 16384 elements
    out[4 * PN + i] = 0.f;
}

// ---------------------------------------------------------------------------
// Kernel 3: per-(plane, point-chunk) masks + compacted masked max-pool.
// grid = (N/2048, P), 256 threads, 4 points/thread x 2 iters, vector I/O.
// ---------------------------------------------------------------------------
#define P2_TPB 256
#define P2_PTS 2048
#define P2_ITERS 2

__global__ void __launch_bounds__(P2_TPB) plane_kernel(
    const float* __restrict__ xyz, const float* __restrict__ centers,
    const float* __restrict__ plane_center, const float* __restrict__ plane_normal,
    const float* __restrict__ pmin, const float* __restrict__ pmax,
    float* __restrict__ out)
{
    const int p = blockIdx.y;
    const int base = blockIdx.x * P2_PTS;
    const int tid = threadIdx.x;

    __shared__ unsigned shOn[64], shOff[64];
    __shared__ int lstOn[P2_PTS];
    __shared__ int lstOff[P2_PTS];
    __shared__ int cntOn, cntOff;
    if (tid == 0) { cntOn = 0; cntOff = 0; }
    if (tid < 64) { shOn[tid] = 0u; shOff[tid] = 0u; }

    const float nx = plane_normal[p * 3 + 0];
    const float ny = plane_normal[p * 3 + 1];
    const float nz = plane_normal[p * 3 + 2];
    const float off = plane_center[p * 3 + 0] * nx
                    + plane_center[p * 3 + 1] * ny
                    + plane_center[p * 3 + 2] * nz;
    const float mn0 = pmin[p * 3 + 0], mn1 = pmin[p * 3 + 1], mn2 = pmin[p * 3 + 2];
    const float mx0 = pmax[p * 3 + 0], mx1 = pmax[p * 3 + 1], mx2 = pmax[p * 3 + 2];
    const bool a0 = (mx0 != 0.f), a1 = (mx1 != 0.f), a2 = (mx2 != 0.f);
    const float cx = centers[0], cy = centers[1], cz = centers[2];

    __syncthreads();

    float* oS  = out;
    float* oM  = out + PN;
    float* oOn = out + 2 * PN;
    float* oOf = out + 3 * PN;
    const size_t rowoff = (size_t)p * NPTS;

    #pragma unroll
    for (int i = 0; i < P2_ITERS; i++) {
        const int n = base + (i * P2_TPB + tid) * 4;     // n % 4 == 0
        // 4 points' xyz = 12 contiguous floats (3n % 4 == 0 -> float4 aligned)
        const float4* xp = (const float4*)(xyz + (size_t)n * 3);
        float4 q0 = xp[0], q1 = xp[1], q2 = xp[2];
        float X[4] = {q0.x, q0.w, q1.z, q2.y};
        float Y[4] = {q0.y, q1.x, q1.w, q2.z};
        float Z[4] = {q0.z, q1.y, q2.x, q2.w};
        float4 sc = *(const float4*)(g_scores + n);
        float S[4] = {sc.x, sc.y, sc.z, sc.w};

        float4 vS, vM, vOn, vOf;
        float* pS  = &vS.x;
        float* pM  = &vM.x;
        float* pOn = &vOn.x;
        float* pOf = &vOf.x;
        #pragma unroll
        for (int u = 0; u < 4; u++) {
            float px = X[u] + cx, py = Y[u] + cy, pz = Z[u] + cz;
            bool rok = (!a0 || (px >= mn0 && px < mx0))
                    && (!a1 || (py >= mn1 && py < mx1))
                    && (!a2 || (pz >= mn2 && pz < mx2));
            float dist = fabsf(px * nx + py * ny + pz * nz - off);
            bool mask = rok && (dist < 0.1f);
            float s = S[u];
            // sigmoid(s) > 0.5  <=>  s > 0   (s >= 0 from relu)
            bool onm  = mask && (s > 0.f);
            bool offm = mask && (s <= 0.f);
            pS[u]  = mask ? s : 0.f;
            pM[u]  = mask ? 1.f : 0.f;
            pOn[u] = onm ? 1.f : 0.f;
            pOf[u] = offm ? 1.f : 0.f;
            if (onm)       lstOn[atomicAdd(&cntOn, 1)] = n + u;
            else if (offm) lstOff[atomicAdd(&cntOff, 1)] = n + u;
        }
        const size_t o = rowoff + n;
        *(float4*)(oS + o)  = vS;
        *(float4*)(oM + o)  = vM;
        *(float4*)(oOn + o) = vOn;
        *(float4*)(oOf + o) = vOf;
    }
    __syncthreads();

    // Cooperative masked max-pool of h2 rows: 4 rows in flight x 64 dims.
    const int d = tid & 63;
    const int g = tid >> 6;
    unsigned mOn = 0u, mOf = 0u;
    const int con = cntOn, cof = cntOff;
    for (int idx = g; idx < con; idx += 4) {
        int nn = lstOn[idx];
        mOn = max(mOn, __float_as_uint(g_h2[(size_t)nn * 64 + d]));
    }
    for (int idx = g; idx < cof; idx += 4) {
        int nn = lstOff[idx];
        mOf = max(mOf, __float_as_uint(g_h2[(size_t)nn * 64 + d]));
    }
    if (mOn) atomicMax(&shOn[d], mOn);
    if (mOf) atomicMax(&shOff[d], mOf);
    __syncthreads();

    // h2 >= 0 so uint-bit atomicMax against 0-initialized output is exact.
    if (tid < 64) {
        unsigned v = shOn[tid];
        if (v) atomicMax((unsigned*)(out + 4 * PN + (size_t)p * 64 + tid), v);
    } else if (tid < 128) {
        unsigned v = shOff[tid - 64];
        if (v) atomicMax((unsigned*)(out + 4 * PN + (size_t)PPL * 64 + (size_t)p * 64 + (tid - 64)), v);
    }
}

// ---------------------------------------------------------------------------
extern "C" void kernel_launch(void* const* d_in, const int* in_sizes, int n_in,
                              void* d_out, int out_size) {
    const float* feature      = (const float*)d_in[0];
    const float* feature_geo  = (const float*)d_in[1];
    const float* xyz          = (const float*)d_in[2];
    const float* centers      = (const float*)d_in[3];
    const float* plane_center = (const float*)d_in[4];
    const float* plane_normal = (const float*)d_in[5];
    const float* pxyz_min     = (const float*)d_in[6];
    const float* pxyz_max     = (const float*)d_in[7];
    const float* w1 = (const float*)d_in[8];
    const float* b1 = (const float*)d_in[9];
    const float* g1 = (const float*)d_in[10];
    const float* be1 = (const float*)d_in[11];
    const float* m1 = (const float*)d_in[12];
    const float* v1 = (const float*)d_in[13];
    const float* w2 = (const float*)d_in[14];
    const float* b2 = (const float*)d_in[15];
    const float* g2 = (const float*)d_in[16];
    const float* be2 = (const float*)d_in[17];
    const float* m2 = (const float*)d_in[18];
    const float* v2 = (const float*)d_in[19];
    const float* w3 = (const float*)d_in[20];
    const float* b3 = (const float*)d_in[21];
    float* out = (float*)d_out;

    cudaFuncSetAttribute((const void*)mlp_kernel,
                         cudaFuncAttributeMaxDynamicSharedMemorySize,
                         MLP_SMEM_BYTES);

    zero_feats<<<64, 256>>>(out);
    mlp_kernel<<<NPTS / MLP_TPB, MLP_TPB, MLP_SMEM_BYTES>>>(
        feature, feature_geo,
        w1, b1, g1, be1, m1, v1,
        w2, b2, g2, be2, m2, v2,
        w3, b3);
    dim3 grid2(NPTS / P2_PTS, PPL);
    plane_kernel<<<grid2, P2_TPB>>>(xyz, centers, plane_center, plane_normal,
                                    pxyz_min, pxyz_max, out);
}

// round 6
// speedup vs baseline: 1.2204x; 1.1645x over previous
#include <cuda_runtime.h>

#define NPTS 262144
#define PPL 128
#define DD 64
#define PN ((size_t)PPL * (size_t)NPTS)

typedef unsigned long long u64;

// Scratch (no allocation allowed -> __device__ globals)
__device__ float g_h2[(size_t)NPTS * DD];   // 64 MB: fc2 features (post BN+ReLU)
__device__ float g_scores[NPTS];            // 1 MB : relu(fc3) scores

// ---------------------------------------------------------------------------
// Packed f32x2 helpers (FFMA2 — bit-exact pair of fp32 FMAs)
// ---------------------------------------------------------------------------
__device__ __forceinline__ u64 pack_dup(float x) {
    u64 r;
    asm("mov.b64 %0, {%1, %1};" : "=l"(r) : "f"(x));
    return r;
}
__device__ __forceinline__ u64 pack2(float lo, float hi) {
    u64 r;
    asm("mov.b64 %0, {%1, %2};" : "=l"(r) : "f"(lo), "f"(hi));
    return r;
}
__device__ __forceinline__ void unpack2(u64 v, float& lo, float& hi) {
    asm("mov.b64 {%0, %1}, %2;" : "=f"(lo), "=f"(hi) : "l"(v));
}
__device__ __forceinline__ void ffma2(u64& acc, u64 a, u64 b) {
    asm("fma.rn.f32x2 %0, %1, %2, %0;" : "+l"(acc) : "l"(a), "l"(b));
}

// ---------------------------------------------------------------------------
// Kernel 1: per-point MLP. Block = 128 points x 64 channels.
// Thread tile = 8 points x 8 channels: per k-step only 4 LDS.128 + 32 FFMA2.
// ---------------------------------------------------------------------------
#define MLP_TPB 128
#define FSTR 132                           // act-tile row stride (16B-aligned rows)
#define SH_W_FLOATS 4096                   // 64x64 weight tile
#define SH_F_FLOATS (64 * FSTR)            // transposed activation tile [k][pt]
#define MLP_SMEM_BYTES ((SH_W_FLOATS + SH_F_FLOATS) * 4)

__global__ void __launch_bounds__(MLP_TPB) mlp_kernel(
    const float* __restrict__ feature, const float* __restrict__ feature_geo,
    const float* __restrict__ w1, const float* __restrict__ b1,
    const float* __restrict__ g1, const float* __restrict__ be1,
    const float* __restrict__ m1, const float* __restrict__ v1,
    const float* __restrict__ w2, const float* __restrict__ b2,
    const float* __restrict__ g2, const float* __restrict__ be2,
    const float* __restrict__ m2, const float* __restrict__ v2,
    const float* __restrict__ w3, const float* __restrict__ b3)
{
    extern __shared__ float smem[];
    float* sh_w = smem;                 // SH_W_FLOATS
    float* sh_f = smem + SH_W_FLOATS;   // SH_F_FLOATS

    __shared__ float A1[64], C1[64], A2[64], C2[64], W3s[64];
    __shared__ float sh_s[128 * 8];     // per-(point, ch-group) fc3 partials
    __shared__ float B3;

    const int tid = threadIdx.x;
    const int pg  = tid & 15;           // point group: points 8*pg .. 8*pg+7
    const int cg  = tid >> 4;           // chan group : chans  8*cg .. 8*cg+7
    const int base = blockIdx.x * MLP_TPB;

    // Fold BN into per-channel scale/offset: relu(acc*A + C)
    if (tid < 64) {
        float s1 = g1[tid] * rsqrtf(v1[tid] + 1e-5f);
        A1[tid] = s1;
        C1[tid] = (b1[tid] - m1[tid]) * s1 + be1[tid];
        float s2 = g2[tid] * rsqrtf(v2[tid] + 1e-5f);
        A2[tid] = s2;
        C2[tid] = (b2[tid] - m2[tid]) * s2 + be2[tid];
        W3s[tid] = w3[tid];
        if (tid == 0) B3 = b3[0];
    }

    u64 acc[32];                        // acc[p*4 + j] = chans (8cg+2j, 8cg+2j+1), point 8pg+p
    #pragma unroll
    for (int i = 0; i < 32; i++) acc[i] = 0ull;

    // ---- Layer 1: K=128 in two halves (half 0 = feature, half 1 = feature_geo)
    for (int kh = 0; kh < 2; kh++) {
        __syncthreads();  // buffers free to overwrite (also covers A1/C1 init)
        {
            const float4* wsrc = (const float4*)(w1 + kh * 4096);
            float4* wdst = (float4*)sh_w;
            #pragma unroll
            for (int i = tid; i < 1024; i += MLP_TPB) wdst[i] = wsrc[i];
        }
        {   // stage activations transposed: sh_f[k][pt]
            const float* src = kh ? feature_geo : feature;
            const float4* fsrc = (const float4*)(src + (size_t)base * 64);
            #pragma unroll
            for (int idx = tid; idx < 2048; idx += MLP_TPB) {
                float4 v = fsrc[idx];
                int pt = idx >> 4;
                int kk = (idx & 15) * 4;
                sh_f[(kk + 0) * FSTR + pt] = v.x;
                sh_f[(kk + 1) * FSTR + pt] = v.y;
                sh_f[(kk + 2) * FSTR + pt] = v.z;
                sh_f[(kk + 3) * FSTR + pt] = v.w;
            }
        }
        __syncthreads();
        #pragma unroll 4
        for (int kk = 0; kk < 64; kk++) {
            const float4* ar = (const float4*)(sh_f + kk * FSTR + 8 * pg);
            float4 a0 = ar[0], a1 = ar[1];
            const float4* wr = (const float4*)(sh_w + kk * 64 + 8 * cg);
            float4 wv0 = wr[0], wv1 = wr[1];
            u64 wp0 = pack2(wv0.x, wv0.y), wp1 = pack2(wv0.z, wv0.w);
            u64 wp2 = pack2(wv1.x, wv1.y), wp3 = pack2(wv1.z, wv1.w);
            float av[8] = {a0.x, a0.y, a0.z, a0.w, a1.x, a1.y, a1.z, a1.w};
            #pragma unroll
            for (int p = 0; p < 8; p++) {
                u64 ad = pack_dup(av[p]);
                ffma2(acc[p * 4 + 0], ad, wp0);
                ffma2(acc[p * 4 + 1], ad, wp1);
                ffma2(acc[p * 4 + 2], ad, wp2);
                ffma2(acc[p * 4 + 3], ad, wp3);
            }
        }
    }

    __syncthreads();  // all reads of sh_f (acts) and sh_w (w1) done

    // BN1 + ReLU -> h1 transposed into sh_f rows 8cg..8cg+7, cols 8pg..8pg+7.
    #pragma unroll
    for (int p = 0; p < 8; p++) {
        #pragma unroll
        for (int j = 0; j < 4; j++) {
            float lo, hi;
            unpack2(acc[p * 4 + j], lo, hi);
            int c0 = 8 * cg + 2 * j;
            sh_f[(c0 + 0) * FSTR + 8 * pg + p] =
                fmaxf(fmaf(lo, A1[c0 + 0], C1[c0 + 0]), 0.f);
            sh_f[(c0 + 1) * FSTR + 8 * pg + p] =
                fmaxf(fmaf(hi, A1[c0 + 1], C1[c0 + 1]), 0.f);
            acc[p * 4 + j] = 0ull;
        }
    }
    {   // stage w2 (disjoint smem region, concurrent with h1 writes)
        const float4* wsrc = (const float4*)w2;
        float4* wdst = (float4*)sh_w;
        #pragma unroll
        for (int i = tid; i < 1024; i += MLP_TPB) wdst[i] = wsrc[i];
    }
    __syncthreads();

    // ---- Layer 2: K=64
    #pragma unroll 4
    for (int kk = 0; kk < 64; kk++) {
        const float4* ar = (const float4*)(sh_f + kk * FSTR + 8 * pg);
        float4 a0 = ar[0], a1 = ar[1];
        const float4* wr = (const float4*)(sh_w + kk * 64 + 8 * cg);
        float4 wv0 = wr[0], wv1 = wr[1];
        u64 wp0 = pack2(wv0.x, wv0.y), wp1 = pack2(wv0.z, wv0.w);
        u64 wp2 = pack2(wv1.x, wv1.y), wp3 = pack2(wv1.z, wv1.w);
        float av[8] = {a0.x, a0.y, a0.z, a0.w, a1.x, a1.y, a1.z, a1.w};
        #pragma unroll
        for (int p = 0; p < 8; p++) {
            u64 ad = pack_dup(av[p]);
            ffma2(acc[p * 4 + 0], ad, wp0);
            ffma2(acc[p * 4 + 1], ad, wp1);
            ffma2(acc[p * 4 + 2], ad, wp2);
            ffma2(acc[p * 4 + 3], ad, wp3);
        }
    }

    // BN2 + ReLU -> h2 (direct STG.128), fc3 partials into sh_s
    #pragma unroll
    for (int p = 0; p < 8; p++) {
        float v[8];
        #pragma unroll
        for (int j = 0; j < 4; j++) unpack2(acc[p * 4 + j], v[2 * j], v[2 * j + 1]);
        float s = 0.f;
        #pragma unroll
        for (int j = 0; j < 8; j++) {
            int c = 8 * cg + j;
            v[j] = fmaxf(fmaf(v[j], A2[c], C2[c]), 0.f);
            s = fmaf(v[j], W3s[c], s);
        }
        float* hrow = g_h2 + (size_t)(base + 8 * pg + p) * 64 + 8 * cg;
        ((float4*)hrow)[0] = make_float4(v[0], v[1], v[2], v[3]);
        ((float4*)hrow)[1] = make_float4(v[4], v[5], v[6], v[7]);
        sh_s[(8 * pg + p) * 8 + cg] = s;
    }
    __syncthreads();

    // Final fc3 reduce: thread tid owns point tid
    {
        const float* sp = sh_s + tid * 8;
        float s = B3;
        #pragma unroll
        for (int j = 0; j < 8; j++) s += sp[j];
        g_scores[base + tid] = fmaxf(s, 0.f);
    }
}

// ---------------------------------------------------------------------------
// Kernel 2: zero the pooled-feature region (atomicMax accumulates into it)
// ---------------------------------------------------------------------------
__global__ void zero_feats(float* __restrict__ out) {
    size_t i = (size_t)blockIdx.x * 256 + threadIdx.x;  // 16384 elements
    out[4 * PN + i] = 0.f;
}

// ---------------------------------------------------------------------------
// Kernel 3: per-(plane, point-chunk) masks + compacted masked max-pool.
// grid = (N/2048, P), 256 threads, 4 points/thread x 2 iters, vector I/O.
// ---------------------------------------------------------------------------
#define P2_TPB 256
#define P2_PTS 2048
#define P2_ITERS 2

__global__ void __launch_bounds__(P2_TPB) plane_kernel(
    const float* __restrict__ xyz, const float* __restrict__ centers,
    const float* __restrict__ plane_center, const float* __restrict__ plane_normal,
    const float* __restrict__ pmin, const float* __restrict__ pmax,
    float* __restrict__ out)
{
    const int p = blockIdx.y;
    const int base = blockIdx.x * P2_PTS;
    const int tid = threadIdx.x;

    __shared__ unsigned shOn[64], shOff[64];
    __shared__ int lstOn[P2_PTS];
    __shared__ int lstOff[P2_PTS];
    __shared__ int cntOn, cntOff;
    if (tid == 0) { cntOn = 0; cntOff = 0; }
    if (tid < 64) { shOn[tid] = 0u; shOff[tid] = 0u; }

    const float nx = plane_normal[p * 3 + 0];
    const float ny = plane_normal[p * 3 + 1];
    const float nz = plane_normal[p * 3 + 2];
    const float off = plane_center[p * 3 + 0] * nx
                    + plane_center[p * 3 + 1] * ny
                    + plane_center[p * 3 + 2] * nz;
    const float mn0 = pmin[p * 3 + 0], mn1 = pmin[p * 3 + 1], mn2 = pmin[p * 3 + 2];
    const float mx0 = pmax[p * 3 + 0], mx1 = pmax[p * 3 + 1], mx2 = pmax[p * 3 + 2];
    const bool a0 = (mx0 != 0.f), a1 = (mx1 != 0.f), a2 = (mx2 != 0.f);
    const float cx = centers[0], cy = centers[1], cz = centers[2];

    __syncthreads();

    float* oS  = out;
    float* oM  = out + PN;
    float* oOn = out + 2 * PN;
    float* oOf = out + 3 * PN;
    const size_t rowoff = (size_t)p * NPTS;

    #pragma unroll
    for (int i = 0; i < P2_ITERS; i++) {
        const int n = base + (i * P2_TPB + tid) * 4;     // n % 4 == 0
        const float4* xp = (const float4*)(xyz + (size_t)n * 3);
        float4 q0 = xp[0], q1 = xp[1], q2 = xp[2];
        float X[4] = {q0.x, q0.w, q1.z, q2.y};
        float Y[4] = {q0.y, q1.x, q1.w, q2.z};
        float Z[4] = {q0.z, q1.y, q2.x, q2.w};
        float4 sc = *(const float4*)(g_scores + n);
        float S[4] = {sc.x, sc.y, sc.z, sc.w};

        float4 vS, vM, vOn, vOf;
        float* pS  = &vS.x;
        float* pM  = &vM.x;
        float* pOn = &vOn.x;
        float* pOf = &vOf.x;
        #pragma unroll
        for (int u = 0; u < 4; u++) {
            float px = X[u] + cx, py = Y[u] + cy, pz = Z[u] + cz;
            bool rok = (!a0 || (px >= mn0 && px < mx0))
                    && (!a1 || (py >= mn1 && py < mx1))
                    && (!a2 || (pz >= mn2 && pz < mx2));
            float dist = fabsf(px * nx + py * ny + pz * nz - off);
            bool mask = rok && (dist < 0.1f);
            float s = S[u];
            // sigmoid(s) > 0.5  <=>  s > 0   (s >= 0 from relu)
            bool onm  = mask && (s > 0.f);
            bool offm = mask && (s <= 0.f);
            pS[u]  = mask ? s : 0.f;
            pM[u]  = mask ? 1.f : 0.f;
            pOn[u] = onm ? 1.f : 0.f;
            pOf[u] = offm ? 1.f : 0.f;
            if (onm)       lstOn[atomicAdd(&cntOn, 1)] = n + u;
            else if (offm) lstOff[atomicAdd(&cntOff, 1)] = n + u;
        }
        const size_t o = rowoff + n;
        *(float4*)(oS + o)  = vS;
        *(float4*)(oM + o)  = vM;
        *(float4*)(oOn + o) = vOn;
        *(float4*)(oOf + o) = vOf;
    }
    __syncthreads();

    // Cooperative masked max-pool of h2 rows: 4 rows in flight x 64 dims.
    const int d = tid & 63;
    const int g = tid >> 6;
    unsigned mOn = 0u, mOf = 0u;
    const int con = cntOn, cof = cntOff;
    for (int idx = g; idx < con; idx += 4) {
        int nn = lstOn[idx];
        mOn = max(mOn, __float_as_uint(g_h2[(size_t)nn * 64 + d]));
    }
    for (int idx = g; idx < cof; idx += 4) {
        int nn = lstOff[idx];
        mOf = max(mOf, __float_as_uint(g_h2[(size_t)nn * 64 + d]));
    }
    if (mOn) atomicMax(&shOn[d], mOn);
    if (mOf) atomicMax(&shOff[d], mOf);
    __syncthreads();

    // h2 >= 0 so uint-bit atomicMax against 0-initialized output is exact.
    if (tid < 64) {
        unsigned v = shOn[tid];
        if (v) atomicMax((unsigned*)(out + 4 * PN + (size_t)p * 64 + tid), v);
    } else if (tid < 128) {
        unsigned v = shOff[tid - 64];
        if (v) atomicMax((unsigned*)(out + 4 * PN + (size_t)PPL * 64 + (size_t)p * 64 + (tid - 64)), v);
    }
}

// ---------------------------------------------------------------------------
extern "C" void kernel_launch(void* const* d_in, const int* in_sizes, int n_in,
                              void* d_out, int out_size) {
    const float* feature      = (const float*)d_in[0];
    const float* feature_geo  = (const float*)d_in[1];
    const float* xyz          = (const float*)d_in[2];
    const float* centers      = (const float*)d_in[3];
    const float* plane_center = (const float*)d_in[4];
    const float* plane_normal = (const float*)d_in[5];
    const float* pxyz_min     = (const float*)d_in[6];
    const float* pxyz_max     = (const float*)d_in[7];
    const float* w1 = (const float*)d_in[8];
    const float* b1 = (const float*)d_in[9];
    const float* g1 = (const float*)d_in[10];
    const float* be1 = (const float*)d_in[11];
    const float* m1 = (const float*)d_in[12];
    const float* v1 = (const float*)d_in[13];
    const float* w2 = (const float*)d_in[14];
    const float* b2 = (const float*)d_in[15];
    const float* g2 = (const float*)d_in[16];
    const float* be2 = (const float*)d_in[17];
    const float* m2 = (const float*)d_in[18];
    const float* v2 = (const float*)d_in[19];
    const float* w3 = (const float*)d_in[20];
    const float* b3 = (const float*)d_in[21];
    float* out = (float*)d_out;

    cudaFuncSetAttribute((const void*)mlp_kernel,
                         cudaFuncAttributeMaxDynamicSharedMemorySize,
                         MLP_SMEM_BYTES);

    zero_feats<<<64, 256>>>(out);
    mlp_kernel<<<NPTS / MLP_TPB, MLP_TPB, MLP_SMEM_BYTES>>>(
        feature, feature_geo,
        w1, b1, g1, be1, m1, v1,
        w2, b2, g2, be2, m2, v2,
        w3, b3);
    dim3 grid2(NPTS / P2_PTS, PPL);
    plane_kernel<<<grid2, P2_TPB>>>(xyz, centers, plane_center, plane_normal,
                                    pxyz_min, pxyz_max, out);
}

// round 7
// speedup vs baseline: 1.3927x; 1.1412x over previous
#include <cuda_runtime.h>

#define NPTS 262144
#define PPL 128
#define DD 64
#define PN ((size_t)PPL * (size_t)NPTS)

typedef unsigned long long u64;

// Scratch (no allocation allowed -> __device__ globals)
__device__ float g_h2[(size_t)NPTS * DD];   // 64 MB: fc2 features (post BN+ReLU)
__device__ float g_scores[NPTS];            // 1 MB : relu(fc3) scores

// ---------------------------------------------------------------------------
// Packed f32x2 helpers (FFMA2 — bit-exact pair of fp32 FMAs)
// ---------------------------------------------------------------------------
__device__ __forceinline__ u64 pack_dup(float x) {
    u64 r;
    asm("mov.b64 %0, {%1, %1};" : "=l"(r) : "f"(x));
    return r;
}
__device__ __forceinline__ u64 pack2(float lo, float hi) {
    u64 r;
    asm("mov.b64 %0, {%1, %2};" : "=l"(r) : "f"(lo), "f"(hi));
    return r;
}
__device__ __forceinline__ void unpack2(u64 v, float& lo, float& hi) {
    asm("mov.b64 {%0, %1}, %2;" : "=f"(lo), "=f"(hi) : "l"(v));
}
__device__ __forceinline__ void ffma2(u64& acc, u64 a, u64 b) {
    asm("fma.rn.f32x2 %0, %1, %2, %0;" : "+l"(acc) : "l"(a), "l"(b));
}

// ---------------------------------------------------------------------------
// Kernel 1: per-point MLP. Block = 128 points x 64 channels.
// Thread tile = 8 points x 8 channels. Activations kept POINT-MAJOR in smem
// (no transpose) with quad XOR-swizzle q ^ ((pt>>3)&7):
//   - staging = straight float4 STS, conflict-free
//   - compute gather = 8 LDS.128 per k-quad, ~2-way conflicts
// ---------------------------------------------------------------------------
#define MLP_TPB 128
#define SH_W_FLOATS 4096                   // 64x64 weight tile (16 KB)
#define SH_A_FLOATS (128 * 64)             // point-major activation tile (32 KB)
#define MLP_SMEM_BYTES ((SH_W_FLOATS + SH_A_FLOATS) * 4)

__global__ void __launch_bounds__(MLP_TPB) mlp_kernel(
    const float* __restrict__ feature, const float* __restrict__ feature_geo,
    const float* __restrict__ w1, const float* __restrict__ b1,
    const float* __restrict__ g1, const float* __restrict__ be1,
    const float* __restrict__ m1, const float* __restrict__ v1,
    const float* __restrict__ w2, const float* __restrict__ b2,
    const float* __restrict__ g2, const float* __restrict__ be2,
    const float* __restrict__ m2, const float* __restrict__ v2,
    const float* __restrict__ w3, const float* __restrict__ b3)
{
    extern __shared__ float smem[];
    float* sh_w = smem;                 // SH_W_FLOATS
    float4* sh_a = (float4*)(smem + SH_W_FLOATS);   // [pt*16 + swizzled quad]

    __shared__ float A1[64], C1[64], A2[64], C2[64], W3s[64];
    __shared__ float sh_s[128 * 8];     // per-(point, ch-group) fc3 partials
    __shared__ float B3;

    const int tid = threadIdx.x;
    const int pg  = tid & 15;           // point group: points 8*pg .. 8*pg+7
    const int cg  = tid >> 4;           // chan group : chans  8*cg .. 8*cg+7
    const int swz = pg & 7;             // quad swizzle for this thread's points
    const int base = blockIdx.x * MLP_TPB;

    // Fold BN into per-channel scale/offset: relu(acc*A + C)
    if (tid < 64) {
        float s1 = g1[tid] * rsqrtf(v1[tid] + 1e-5f);
        A1[tid] = s1;
        C1[tid] = (b1[tid] - m1[tid]) * s1 + be1[tid];
        float s2 = g2[tid] * rsqrtf(v2[tid] + 1e-5f);
        A2[tid] = s2;
        C2[tid] = (b2[tid] - m2[tid]) * s2 + be2[tid];
        W3s[tid] = w3[tid];
        if (tid == 0) B3 = b3[0];
    }

    u64 acc[32];                        // acc[p*4 + j] = chans (8cg+2j, 8cg+2j+1), point 8pg+p
    #pragma unroll
    for (int i = 0; i < 32; i++) acc[i] = 0ull;

    // ---- Layer 1: K=128 in two halves (half 0 = feature, half 1 = feature_geo)
    for (int kh = 0; kh < 2; kh++) {
        if (kh) __syncthreads();        // previous compute done with buffers
        {   // stage weight half: w1 rows [kh*64, kh*64+64)
            const float4* wsrc = (const float4*)(w1 + kh * 4096);
            float4* wdst = (float4*)sh_w;
            #pragma unroll
            for (int i = tid; i < 1024; i += MLP_TPB) wdst[i] = wsrc[i];
        }
        {   // stage activations point-major, quad-swizzled (conflict-free STS.128)
            const float* src = kh ? feature_geo : feature;
            const float4* fsrc = (const float4*)(src + (size_t)base * 64);
            #pragma unroll
            for (int idx = tid; idx < 2048; idx += MLP_TPB) {
                int pt = idx >> 4;
                int q  = idx & 15;
                sh_a[pt * 16 + (q ^ ((pt >> 3) & 7))] = fsrc[idx];
            }
        }
        __syncthreads();
        #pragma unroll 2
        for (int kq = 0; kq < 16; kq++) {
            float4 aq[8];
            #pragma unroll
            for (int p = 0; p < 8; p++)
                aq[p] = sh_a[(8 * pg + p) * 16 + (kq ^ swz)];
            #pragma unroll
            for (int j = 0; j < 4; j++) {
                const float4* wr = (const float4*)(sh_w + (4 * kq + j) * 64 + 8 * cg);
                float4 wv0 = wr[0], wv1 = wr[1];
                u64 wp0 = pack2(wv0.x, wv0.y), wp1 = pack2(wv0.z, wv0.w);
                u64 wp2 = pack2(wv1.x, wv1.y), wp3 = pack2(wv1.z, wv1.w);
                #pragma unroll
                for (int p = 0; p < 8; p++) {
                    float a = (j == 0) ? aq[p].x : (j == 1) ? aq[p].y
                            : (j == 2) ? aq[p].z : aq[p].w;
                    u64 ad = pack_dup(a);
                    ffma2(acc[p * 4 + 0], ad, wp0);
                    ffma2(acc[p * 4 + 1], ad, wp1);
                    ffma2(acc[p * 4 + 2], ad, wp2);
                    ffma2(acc[p * 4 + 3], ad, wp3);
                }
            }
        }
    }

    __syncthreads();  // all reads of sh_a (acts) and sh_w (w1) done

    // BN1 + ReLU -> h1 back into sh_a (point-major, same swizzle), as float4s
    #pragma unroll
    for (int p = 0; p < 8; p++) {
        float v[8];
        #pragma unroll
        for (int j = 0; j < 4; j++) unpack2(acc[p * 4 + j], v[2 * j], v[2 * j + 1]);
        float4 lo, hi;
        lo.x = fmaxf(fmaf(v[0], A1[8 * cg + 0], C1[8 * cg + 0]), 0.f);
        lo.y = fmaxf(fmaf(v[1], A1[8 * cg + 1], C1[8 * cg + 1]), 0.f);
        lo.z = fmaxf(fmaf(v[2], A1[8 * cg + 2], C1[8 * cg + 2]), 0.f);
        lo.w = fmaxf(fmaf(v[3], A1[8 * cg + 3], C1[8 * cg + 3]), 0.f);
        hi.x = fmaxf(fmaf(v[4], A1[8 * cg + 4], C1[8 * cg + 4]), 0.f);
        hi.y = fmaxf(fmaf(v[5], A1[8 * cg + 5], C1[8 * cg + 5]), 0.f);
        hi.z = fmaxf(fmaf(v[6], A1[8 * cg + 6], C1[8 * cg + 6]), 0.f);
        hi.w = fmaxf(fmaf(v[7], A1[8 * cg + 7], C1[8 * cg + 7]), 0.f);
        int qb = (8 * pg + p) * 16;
        sh_a[qb + ((2 * cg + 0) ^ swz)] = lo;
        sh_a[qb + ((2 * cg + 1) ^ swz)] = hi;
        acc[p * 4 + 0] = 0ull; acc[p * 4 + 1] = 0ull;
        acc[p * 4 + 2] = 0ull; acc[p * 4 + 3] = 0ull;
    }
    {   // stage w2 (disjoint smem region, concurrent with h1 writes)
        const float4* wsrc = (const float4*)w2;
        float4* wdst = (float4*)sh_w;
        #pragma unroll
        for (int i = tid; i < 1024; i += MLP_TPB) wdst[i] = wsrc[i];
    }
    __syncthreads();

    // ---- Layer 2: K=64
    #pragma unroll 2
    for (int kq = 0; kq < 16; kq++) {
        float4 aq[8];
        #pragma unroll
        for (int p = 0; p < 8; p++)
            aq[p] = sh_a[(8 * pg + p) * 16 + (kq ^ swz)];
        #pragma unroll
        for (int j = 0; j < 4; j++) {
            const float4* wr = (const float4*)(sh_w + (4 * kq + j) * 64 + 8 * cg);
            float4 wv0 = wr[0], wv1 = wr[1];
            u64 wp0 = pack2(wv0.x, wv0.y), wp1 = pack2(wv0.z, wv0.w);
            u64 wp2 = pack2(wv1.x, wv1.y), wp3 = pack2(wv1.z, wv1.w);
            #pragma unroll
            for (int p = 0; p < 8; p++) {
                float a = (j == 0) ? aq[p].x : (j == 1) ? aq[p].y
                        : (j == 2) ? aq[p].z : aq[p].w;
                u64 ad = pack_dup(a);
                ffma2(acc[p * 4 + 0], ad, wp0);
                ffma2(acc[p * 4 + 1], ad, wp1);
                ffma2(acc[p * 4 + 2], ad, wp2);
                ffma2(acc[p * 4 + 3], ad, wp3);
            }
        }
    }

    // BN2 + ReLU -> h2 (direct STG.128), fc3 partials into sh_s
    #pragma unroll
    for (int p = 0; p < 8; p++) {
        float v[8];
        #pragma unroll
        for (int j = 0; j < 4; j++) unpack2(acc[p * 4 + j], v[2 * j], v[2 * j + 1]);
        float s = 0.f;
        #pragma unroll
        for (int j = 0; j < 8; j++) {
            int c = 8 * cg + j;
            v[j] = fmaxf(fmaf(v[j], A2[c], C2[c]), 0.f);
            s = fmaf(v[j], W3s[c], s);
        }
        float* hrow = g_h2 + (size_t)(base + 8 * pg + p) * 64 + 8 * cg;
        ((float4*)hrow)[0] = make_float4(v[0], v[1], v[2], v[3]);
        ((float4*)hrow)[1] = make_float4(v[4], v[5], v[6], v[7]);
        sh_s[(8 * pg + p) * 8 + cg] = s;
    }
    __syncthreads();

    // Final fc3 reduce: thread tid owns point tid
    {
        const float* sp = sh_s + tid * 8;
        float s = B3;
        #pragma unroll
        for (int j = 0; j < 8; j++) s += sp[j];
        g_scores[base + tid] = fmaxf(s, 0.f);
    }
}

// ---------------------------------------------------------------------------
// Kernel 2: zero the pooled-feature region (atomicMax accumulates into it)
// ---------------------------------------------------------------------------
__global__ void zero_feats(float* __restrict__ out) {
    size_t i = (size_t)blockIdx.x * 256 + threadIdx.x;  // 16384 elements
    out[4 * PN + i] = 0.f;
}

// ---------------------------------------------------------------------------
// Kernel 3: per-(plane, point-chunk) masks + compacted masked max-pool.
// grid = (N/2048, P), 256 threads, 4 points/thread x 2 iters, vector I/O.
// Mask outputs use streaming (.cs) stores: written once, keep L2 for h2.
// ---------------------------------------------------------------------------
#define P2_TPB 256
#define P2_PTS 2048
#define P2_ITERS 2

__global__ void __launch_bounds__(P2_TPB) plane_kernel(
    const float* __restrict__ xyz, const float* __restrict__ centers,
    const float* __restrict__ plane_center, const float* __restrict__ plane_normal,
    const float* __restrict__ pmin, const float* __restrict__ pmax,
    float* __restrict__ out)
{
    const int p = blockIdx.y;
    const int base = blockIdx.x * P2_PTS;
    const int tid = threadIdx.x;

    __shared__ unsigned shOn[64], shOff[64];
    __shared__ int lstOn[P2_PTS];
    __shared__ int lstOff[P2_PTS];
    __shared__ int cntOn, cntOff;
    if (tid == 0) { cntOn = 0; cntOff = 0; }
    if (tid < 64) { shOn[tid] = 0u; shOff[tid] = 0u; }

    const float nx = plane_normal[p * 3 + 0];
    const float ny = plane_normal[p * 3 + 1];
    const float nz = plane_normal[p * 3 + 2];
    const float off = plane_center[p * 3 + 0] * nx
                    + plane_center[p * 3 + 1] * ny
                    + plane_center[p * 3 + 2] * nz;
    const float mn0 = pmin[p * 3 + 0], mn1 = pmin[p * 3 + 1], mn2 = pmin[p * 3 + 2];
    const float mx0 = pmax[p * 3 + 0], mx1 = pmax[p * 3 + 1], mx2 = pmax[p * 3 + 2];
    const bool a0 = (mx0 != 0.f), a1 = (mx1 != 0.f), a2 = (mx2 != 0.f);
    const float cx = centers[0], cy = centers[1], cz = centers[2];

    __syncthreads();

    float* oS  = out;
    float* oM  = out + PN;
    float* oOn = out + 2 * PN;
    float* oOf = out + 3 * PN;
    const size_t rowoff = (size_t)p * NPTS;

    #pragma unroll
    for (int i = 0; i < P2_ITERS; i++) {
        const int n = base + (i * P2_TPB + tid) * 4;     // n % 4 == 0
        const float4* xp = (const float4*)(xyz + (size_t)n * 3);
        float4 q0 = xp[0], q1 = xp[1], q2 = xp[2];
        float X[4] = {q0.x, q0.w, q1.z, q2.y};
        float Y[4] = {q0.y, q1.x, q1.w, q2.z};
        float Z[4] = {q0.z, q1.y, q2.x, q2.w};
        float4 sc = *(const float4*)(g_scores + n);
        float S[4] = {sc.x, sc.y, sc.z, sc.w};

        float4 vS, vM, vOn, vOf;
        float* pS  = &vS.x;
        float* pM  = &vM.x;
        float* pOn = &vOn.x;
        float* pOf = &vOf.x;
        #pragma unroll
        for (int u = 0; u < 4; u++) {
            float px = X[u] + cx, py = Y[u] + cy, pz = Z[u] + cz;
            bool rok = (!a0 || (px >= mn0 && px < mx0))
                    && (!a1 || (py >= mn1 && py < mx1))
                    && (!a2 || (pz >= mn2 && pz < mx2));
            float dist = fabsf(px * nx + py * ny + pz * nz - off);
            bool mask = rok && (dist < 0.1f);
            float s = S[u];
            // sigmoid(s) > 0.5  <=>  s > 0   (s >= 0 from relu)
            bool onm  = mask && (s > 0.f);
            bool offm = mask && (s <= 0.f);
            pS[u]  = mask ? s : 0.f;
            pM[u]  = mask ? 1.f : 0.f;
            pOn[u] = onm ? 1.f : 0.f;
            pOf[u] = offm ? 1.f : 0.f;
            if (onm)       lstOn[atomicAdd(&cntOn, 1)] = n + u;
            else if (offm) lstOff[atomicAdd(&cntOff, 1)] = n + u;
        }
        const size_t o = rowoff + n;
        __stcs((float4*)(oS + o),  vS);
        __stcs((float4*)(oM + o),  vM);
        __stcs((float4*)(oOn + o), vOn);
        __stcs((float4*)(oOf + o), vOf);
    }
    __syncthreads();

    // Cooperative masked max-pool of h2 rows: 4 rows in flight x 64 dims.
    const int d = tid & 63;
    const int g = tid >> 6;
    unsigned mOn = 0u, mOf = 0u;
    const int con = cntOn, cof = cntOff;
    for (int idx = g; idx < con; idx += 4) {
        int nn = lstOn[idx];
        mOn = max(mOn, __float_as_uint(g_h2[(size_t)nn * 64 + d]));
    }
    for (int idx = g; idx < cof; idx += 4) {
        int nn = lstOff[idx];
        mOf = max(mOf, __float_as_uint(g_h2[(size_t)nn * 64 + d]));
    }
    if (mOn) atomicMax(&shOn[d], mOn);
    if (mOf) atomicMax(&shOff[d], mOf);
    __syncthreads();

    // h2 >= 0 so uint-bit atomicMax against 0-initialized output is exact.
    if (tid < 64) {
        unsigned v = shOn[tid];
        if (v) atomicMax((unsigned*)(out + 4 * PN + (size_t)p * 64 + tid), v);
    } else if (tid < 128) {
        unsigned v = shOff[tid - 64];
        if (v) atomicMax((unsigned*)(out + 4 * PN + (size_t)PPL * 64 + (size_t)p * 64 + (tid - 64)), v);
    }
}

// ---------------------------------------------------------------------------
extern "C" void kernel_launch(void* const* d_in, const int* in_sizes, int n_in,
                              void* d_out, int out_size) {
    const float* feature      = (const float*)d_in[0];
    const float* feature_geo  = (const float*)d_in[1];
    const float* xyz          = (const float*)d_in[2];
    const float* centers      = (const float*)d_in[3];
    const float* plane_center = (const float*)d_in[4];
    const float* plane_normal = (const float*)d_in[5];
    const float* pxyz_min     = (const float*)d_in[6];
    const float* pxyz_max     = (const float*)d_in[7];
    const float* w1 = (const float*)d_in[8];
    const float* b1 = (const float*)d_in[9];
    const float* g1 = (const float*)d_in[10];
    const float* be1 = (const float*)d_in[11];
    const float* m1 = (const float*)d_in[12];
    const float* v1 = (const float*)d_in[13];
    const float* w2 = (const float*)d_in[14];
    const float* b2 = (const float*)d_in[15];
    const float* g2 = (const float*)d_in[16];
    const float* be2 = (const float*)d_in[17];
    const float* m2 = (const float*)d_in[18];
    const float* v2 = (const float*)d_in[19];
    const float* w3 = (const float*)d_in[20];
    const float* b3 = (const float*)d_in[21];
    float* out = (float*)d_out;

    cudaFuncSetAttribute((const void*)mlp_kernel,
                         cudaFuncAttributeMaxDynamicSharedMemorySize,
                         MLP_SMEM_BYTES);

    mlp_kernel<<<NPTS / MLP_TPB, MLP_TPB, MLP_SMEM_BYTES>>>(
        feature, feature_geo,
        w1, b1, g1, be1, m1, v1,
        w2, b2, g2, be2, m2, v2,
        w3, b3);
    zero_feats<<<64, 256>>>(out);
    dim3 grid2(NPTS / P2_PTS, PPL);
    plane_kernel<<<grid2, P2_TPB>>>(xyz, centers, plane_center, plane_normal,
                                    pxyz_min, pxyz_max, out);
}